// round 17
// baseline (speedup 1.0000x reference)
#include <cuda_runtime.h>
#include <cstdint>

#define M_   4096
#define B_   8
#define N_   512
#define FD_  128
#define BD_  128
#define H_   64
#define TMR  32
#define NTHR 512
#define WST  72        // warp-stage row stride (8 mod 32 -> conflict-free B lds)
#define SCK  0.1803368801111204f   // 0.125 * log2(e)

__device__ float g_BF[B_ * H_ * N_];  // (b, h, n)
__device__ int   g_bar  = 0;
__device__ int   g_exit = 0;

__device__ __forceinline__ void fma2(float2& d, const float2 a, const float2 b) {
    unsigned long long& dd = *reinterpret_cast<unsigned long long*>(&d);
    const unsigned long long aa = *reinterpret_cast<const unsigned long long*>(&a);
    const unsigned long long bb = *reinterpret_cast<const unsigned long long*>(&b);
    asm("fma.rn.f32x2 %0, %1, %2, %0;" : "+l"(dd) : "l"(aa), "l"(bb));
}
__device__ __forceinline__ float2 dup(float s) { return make_float2(s, s); }

__device__ __forceinline__ uint32_t f2tf(float f) {
    uint32_t u;
    asm("cvt.rna.tf32.f32 %0, %1;" : "=r"(u) : "f"(f));
    return u;
}
__device__ __forceinline__ void mma8(float* c, const uint32_t* a,
                                     uint32_t b0, uint32_t b1) {
    asm volatile(
        "mma.sync.aligned.m16n8k8.row.col.f32.tf32.tf32.f32 "
        "{%0,%1,%2,%3}, {%4,%5,%6,%7}, {%8,%9}, {%0,%1,%2,%3};"
        : "+f"(c[0]), "+f"(c[1]), "+f"(c[2]), "+f"(c[3])
        : "r"(a[0]), "r"(a[1]), "r"(a[2]), "r"(a[3]), "r"(b0), "r"(b1));
}

__device__ __forceinline__ uint32_t saddr(const void* p) {
    return (uint32_t)__cvta_generic_to_shared(p);
}
__device__ __forceinline__ void cp16(uint32_t dst, const void* src) {
    asm volatile("cp.async.cg.shared.global [%0], [%1], 16;" :: "r"(dst), "l"(src));
}
#define CP_COMMIT() asm volatile("cp.async.commit_group;")
#define CPW(n)      asm volatile("cp.async.wait_group " #n ";")

// ---------------- per-warp stage: 32k x 64n slice, 4 cp groups -------------
__device__ __forceinline__ void warp_stage(float* wb, const float* gsrc, int l) {
    #pragma unroll
    for (int s = 0; s < 4; s++) {
        #pragma unroll
        for (int t = 0; t < 4; t++) {
            int idx = l + t * 32;
            int row = idx >> 4;
            int col4 = (idx & 15) * 4;
            int rr = s * 8 + row;
            cp16(saddr(wb + rr * WST + col4), gsrc + rr * 512 + col4);
        }
        CP_COMMIT();
    }
}

// ------------------------------- fused kernel ------------------------------
__global__ void __launch_bounds__(NTHR) main_kernel(
    const int* __restrict__ batch, const float* __restrict__ bvin,
    const float* __restrict__ Wbv, const float* __restrict__ bbv,
    const float* __restrict__ Wo, const float* __restrict__ bo,
    const float* __restrict__ fin, const float* __restrict__ Wf,
    const float* __restrict__ bf,  const float* __restrict__ bpre,
    const float* __restrict__ Wb,  const float* __restrict__ bb,
    float* __restrict__ out)
{
    extern __shared__ float sm[];
    float* wstage = sm;           // 16 warps x 32 x WST = 36864
    // phase-0 aliases inside wstage:
    float* Af = sm;               // [0, 4224)        32x132
    float* Bf = sm + 4224;        // [4224, 13440)    128x72  (WfT)
    float* Ab = sm + 13440;       // [13440, 21888)   64x132  (Wb)
    float* Bb = sm + 21888;       // [21888, 27008)   128x40  (bpre slice)
    // post-pass-1 aliases:
    float* WoT   = sm;            // [0, 8704)     [k][j] stride 68
    float* cat   = sm + 9216;     // [9216, 13440) 32x132
    float* bvs   = sm + 36864;    // 6*520 = 3120
    float* Fk    = sm + 39984;    // [2][32][36] = 2304 (scaled by SCK)
    float* red   = sm + 42288;    // [2][8][32] = 512
    float* rinv  = sm + 42800;    // 64
    float* ypart = sm + 42864;    // [2][8][32][3] = 3072
    float* yfin  = sm + 45936;    // [64][6] = 384
    __shared__ int bsh[TMR];

    const int tid = threadIdx.x;
    const int w = tid >> 5, l = tid & 31;
    const int bid = blockIdx.x;
    const int m0 = bid * TMR;
    const int lq = l >> 2, lm = l & 3;

    // ================= phase 0: local F + distributed BF (tf32 MMA) ========
    // stage Af (fin rows), Ab (Wb), Bb (bpre slice) via cp.async
    {
        #pragma unroll
        for (int s = 0; s < 2; s++) {          // Af: 1024 float4
            int i = tid + s * 512;
            int r = i >> 5, d4 = (i & 31) * 4;
            cp16(saddr(Af + r * 132 + d4), fin + (m0 + r) * FD_ + d4);
        }
        #pragma unroll
        for (int s = 0; s < 4; s++) {          // Ab: 2048 float4
            int i = tid + s * 512;
            int h = i >> 5, d4 = (i & 31) * 4;
            cp16(saddr(Ab + h * 132 + d4), Wb + h * BD_ + d4);
        }
        const int unit = bid >> 1;
        const int bb_b = unit >> 3;
        const int n0b  = (unit & 7) * 64 + (bid & 1) * 32;
        #pragma unroll
        for (int s = 0; s < 2; s++) {          // Bb: 1024 float4
            int i = tid + s * 512;
            int d = i >> 3, n4 = (i & 7) * 4;
            cp16(saddr(Bb + d * 40 + n4), bpre + bb_b * (BD_ * N_) + d * N_ + n0b + n4);
        }
        CP_COMMIT();
        // Bf = WfT (transpose, plain LDG+STS)
        for (int i = tid; i < 8192; i += NTHR) {
            int h = i >> 7, d = i & 127;
            Bf[d * 72 + h] = Wf[i];
        }
        CPW(0);
        __syncthreads();

        // ---- F GEMM: warp tile mtf=w&1 (16 rows), ntf=w>>1 (8 cols) -------
        {
            const int mtf = w & 1, ntf = w >> 1;
            float cF[4] = {0.f, 0.f, 0.f, 0.f};
            const float* arow = Af + (mtf * 16 + lq) * 132 + lm;
            #pragma unroll
            for (int ks = 0; ks < 16; ks++) {
                uint32_t A4[4];
                A4[0] = f2tf(arow[ks * 8]);
                A4[1] = f2tf(arow[8 * 132 + ks * 8]);
                A4[2] = f2tf(arow[ks * 8 + 4]);
                A4[3] = f2tf(arow[8 * 132 + ks * 8 + 4]);
                const float* bp = Bf + (ks * 8 + lm) * 72 + ntf * 8 + lq;
                mma8(cF, A4, f2tf(bp[0]), f2tf(bp[4 * 72]));
            }
            const int col = ntf * 8 + 2 * lm;           // h in [0,64)
            const int r0f = mtf * 16 + lq;
            float2 bf2 = *(const float2*)(bf + col);
            float* fk = Fk + (col >> 5) * 1152 + (col & 31);
            *(float2*)(fk + r0f * 36) =
                make_float2((cF[0] + bf2.x) * SCK, (cF[1] + bf2.y) * SCK);
            *(float2*)(fk + (r0f + 8) * 36) =
                make_float2((cF[2] + bf2.x) * SCK, (cF[3] + bf2.y) * SCK);
        }

        // ---- BF GEMM: warp tile mtb=w&3 (16 h-rows), ntb=w>>2 (8 n-cols) --
        {
            const int mtb = w & 3, ntb = w >> 2;
            float cB[4] = {0.f, 0.f, 0.f, 0.f};
            const float* arow = Ab + (mtb * 16 + lq) * 132 + lm;
            #pragma unroll
            for (int ks = 0; ks < 16; ks++) {
                uint32_t A4[4];
                A4[0] = f2tf(arow[ks * 8]);
                A4[1] = f2tf(arow[8 * 132 + ks * 8]);
                A4[2] = f2tf(arow[ks * 8 + 4]);
                A4[3] = f2tf(arow[8 * 132 + ks * 8 + 4]);
                const float* bp = Bb + (ks * 8 + lm) * 40 + ntb * 8 + lq;
                mma8(cB, A4, f2tf(bp[0]), f2tf(bp[4 * 40]));
            }
            const int h0b = mtb * 16 + lq;
            const int ncol = n0b + ntb * 8 + 2 * lm;
            const float bb0 = __ldg(bb + h0b), bb1 = __ldg(bb + h0b + 8);
            *(float2*)(g_BF + bb_b * 32768 + h0b * 512 + ncol) =
                make_float2(cB[0] + bb0, cB[1] + bb0);
            *(float2*)(g_BF + bb_b * 32768 + (h0b + 8) * 512 + ncol) =
                make_float2(cB[2] + bb1, cB[3] + bb1);
        }
    }

    // ================= global barrier (single wave guaranteed) =============
    __threadfence();
    __syncthreads();
    if (tid == 0) atomicAdd(&g_bar, 1);

    // ---- input-only staging overlaps other blocks' phase 0 ----------------
    const int bmin = __ldg(batch + m0);
    const int bmax = __ldg(batch + m0 + TMR - 1);
    const bool uni = (bmin == bmax);
    if (tid < TMR) bsh[tid] = batch[m0 + tid];
    if (uni) {
        for (int i = tid; i < 3072; i += NTHR) {
            int cc = i >> 9, n = i & 511;
            bvs[cc * 520 + n] = bvin[bmin * 6 * N_ + cc * N_ + n];
        }
    }

    if (tid == 0) {
        while (atomicAdd(&g_bar, 0) < 128) {}
        int e = atomicAdd(&g_exit, 1);
        if (e == 127) { atomicExch(&g_bar, 0); atomicExch(&g_exit, 0); }
        __threadfence();
    }
    __syncthreads();

    // ================= main (R15-proven body) ==============================
    const int half = w >> 3;            // warps 0-7: e, 8-15: g
    const int wq   = w & 7;             // n-chunk of 64

    float* wb = wstage + w * (32 * WST);
    if (uni)
        warp_stage(wb, g_BF + bmin * (H_ * N_) + (half * 32) * 512 + wq * 64, l);

    float c[2][8][4];
    #pragma unroll
    for (int mt = 0; mt < 2; mt++)
        #pragma unroll
        for (int nt = 0; nt < 8; nt++)
            #pragma unroll
            for (int q = 0; q < 4; q++) c[mt][nt][q] = 0.f;

    uint32_t A[4][2][4];
    const float* fbase = Fk + half * 1152 + lq * 36 + lm;

#define MMA_CHUNK(S) do { \
        const float* tb = wb + ((S) * 8 + lm) * WST + lq; \
        _Pragma("unroll") \
        for (int nt = 0; nt < 8; nt++) { \
            uint32_t b0 = f2tf(tb[nt * 8]); \
            uint32_t b1 = f2tf(tb[4 * WST + nt * 8]); \
            mma8(c[0][nt], A[S][0], b0, b1); \
            mma8(c[1][nt], A[S][1], b0, b1); \
        } \
    } while (0)

    if (uni) {
        #pragma unroll
        for (int s = 0; s < 4; s++)
            #pragma unroll
            for (int mt = 0; mt < 2; mt++) {
                const float* fb = fbase + mt * 16 * 36 + s * 8;
                A[s][mt][0] = f2tf(fb[0]);
                A[s][mt][1] = f2tf(fb[8 * 36]);
                A[s][mt][2] = f2tf(fb[4]);
                A[s][mt][3] = f2tf(fb[8 * 36 + 4]);
            }
        CPW(3); __syncwarp(); MMA_CHUNK(0);
        CPW(2); __syncwarp(); MMA_CHUNK(1);
        CPW(1); __syncwarp(); MMA_CHUNK(2);
        CPW(0); __syncwarp(); MMA_CHUNK(3);
    } else {
        for (int bc = bmin; bc <= bmax; bc++) {
            warp_stage(wb, g_BF + bc * (H_ * N_) + (half * 32) * 512 + wq * 64, l);
            #pragma unroll
            for (int s = 0; s < 4; s++)
                #pragma unroll
                for (int mt = 0; mt < 2; mt++) {
                    const float* fb = fbase + mt * 16 * 36 + s * 8;
                    bool oklo = (bsh[lq + mt * 16] == bc);
                    bool okhi = (bsh[lq + 8 + mt * 16] == bc);
                    A[s][mt][0] = f2tf(oklo ? fb[0] : 0.f);
                    A[s][mt][1] = f2tf(okhi ? fb[8 * 36] : 0.f);
                    A[s][mt][2] = f2tf(oklo ? fb[4] : 0.f);
                    A[s][mt][3] = f2tf(okhi ? fb[8 * 36 + 4] : 0.f);
                }
            CPW(3); __syncwarp(); MMA_CHUNK(0);
            CPW(2); __syncwarp(); MMA_CHUNK(1);
            CPW(1); __syncwarp(); MMA_CHUNK(2);
            CPW(0); __syncwarp(); MMA_CHUNK(3);
        }
    }
    __syncthreads();   // all pass-1 wstage reads done before WoT/cat alias

    // ---- stage WoT (transpose); overlaps softmax --------------------------
    for (int i = tid; i < 8192; i += NTHR) {
        int j = i >> 7, k = i & 127;
        WoT[k * 68 + j] = Wo[i];
    }

    // =================== softmax: exp2 + sum (scale folded into Fk) ========
    float srow[4];
    #pragma unroll
    for (int j = 0; j < 4; j++) {
        const int mt = j >> 1, hi = (j & 1) * 2;
        float s = 0.f;
        #pragma unroll
        for (int nt = 0; nt < 8; nt++) {
            float e0 = exp2f(c[mt][nt][hi]);
            float e1 = exp2f(c[mt][nt][hi + 1]);
            c[mt][nt][hi] = e0; c[mt][nt][hi + 1] = e1;
            s += e0 + e1;
        }
        srow[j] = s;
    }
    #pragma unroll
    for (int off = 1; off <= 2; off <<= 1)
        #pragma unroll
        for (int j = 0; j < 4; j++)
            srow[j] += __shfl_xor_sync(0xffffffffu, srow[j], off);
    if (lm == 0)
        #pragma unroll
        for (int j = 0; j < 4; j++)
            red[half * 256 + wq * 32 + lq + (j & 1) * 8 + (j >> 1) * 16] = srow[j];
    __syncthreads();
    if (tid < 64) {
        int hh = tid >> 5, r = tid & 31;
        float s = 0.f;
        #pragma unroll
        for (int q = 0; q < 8; q++) s += red[hh * 256 + q * 32 + r];
        rinv[tid] = 1.f / s;
    }
    __syncthreads();

    // =================== pass 2: 6-dim trick ===============================
    #pragma unroll
    for (int cg = 0; cg < 2; cg++) {
        float2 y2[4][3];
        #pragma unroll
        for (int j = 0; j < 4; j++)
            #pragma unroll
            for (int cc = 0; cc < 3; cc++) y2[j][cc] = dup(0.f);

        for (int bc = bmin; bc <= bmax; bc++) {
            if (!uni) {
                __syncthreads();
                for (int i = tid; i < 1536; i += NTHR) {
                    int cc = i >> 9, n = i & 511;
                    bvs[cc * 520 + n] = bvin[bc * 6 * N_ + (cg * 3 + cc) * N_ + n];
                }
                __syncthreads();
            }
            const float* bvbase = uni ? (bvs + cg * 3 * 520) : bvs;

            bool msk[4];
            #pragma unroll
            for (int j = 0; j < 4; j++)
                msk[j] = uni || (bsh[lq + (j & 1) * 8 + (j >> 1) * 16] == bc);

            #pragma unroll
            for (int cc = 0; cc < 3; cc++) {
                const float* bp2 = bvbase + cc * 520 + wq * 64 + 2 * lm;
                #pragma unroll
                for (int nt = 0; nt < 8; nt++) {
                    float2 bv2 = *(const float2*)(bp2 + nt * 8);
                    #pragma unroll
                    for (int j = 0; j < 4; j++) {
                        if (msk[j]) {
                            const int mt = j >> 1, hi = (j & 1) * 2;
                            fma2(y2[j][cc],
                                 make_float2(c[mt][nt][hi], c[mt][nt][hi + 1]), bv2);
                        }
                    }
                }
            }
        }

        float yv[4][3];
        #pragma unroll
        for (int j = 0; j < 4; j++)
            #pragma unroll
            for (int cc = 0; cc < 3; cc++) yv[j][cc] = y2[j][cc].x + y2[j][cc].y;
        #pragma unroll
        for (int off = 1; off <= 2; off <<= 1)
            #pragma unroll
            for (int j = 0; j < 4; j++)
                #pragma unroll
                for (int cc = 0; cc < 3; cc++)
                    yv[j][cc] += __shfl_xor_sync(0xffffffffu, yv[j][cc], off);
        if (lm == 0)
            #pragma unroll
            for (int j = 0; j < 4; j++) {
                int r = lq + (j & 1) * 8 + (j >> 1) * 16;
                #pragma unroll
                for (int cc = 0; cc < 3; cc++)
                    ypart[((half * 8 + wq) * 32 + r) * 3 + cc] = yv[j][cc];
            }
        __syncthreads();
        if (tid < 192) {
            int hh = tid / 96, rem = tid % 96, rr = rem / 3, cc = rem % 3;
            float s = 0.f;
            #pragma unroll
            for (int q = 0; q < 8; q++)
                s += ypart[((hh * 8 + q) * 32 + rr) * 3 + cc];
            yfin[(hh * 32 + rr) * 6 + cg * 3 + cc] = s * rinv[hh * 32 + rr];
        }
        __syncthreads();
    }

    // =================== cat[r][h] = Wbv @ y + bbv =========================
    {
        int r = tid >> 4, hq = (tid & 15) * 4;
        #pragma unroll
        for (int hh = 0; hh < 4; hh++) {
            int h = hq + hh;
            float se = 0.f, sg = 0.f;
            #pragma unroll
            for (int cc = 0; cc < 6; cc++) {
                float wv = __ldg(Wbv + h * 6 + cc);
                se += wv * yfin[r * 6 + cc];
                sg += wv * yfin[(32 + r) * 6 + cc];
            }
            float bb2 = __ldg(bbv + h);
            cat[r * 132 + h]      = se + bb2;
            cat[r * 132 + 64 + h] = sg + bb2;
        }
    }
    __syncthreads();

    // =================== pass 3: out = cat @ Wo.T + bo =====================
    {
        const int j0 = (w & 1) * 32 + (l & 7) * 4;
        const int r  = (w >> 1) * 4 + (l >> 3);
        const float* cr = cat + r * 132;
        float2 olo = dup(0.f), ohi = dup(0.f);
        #pragma unroll 4
        for (int k4 = 0; k4 < 128; k4 += 4) {
            float4 c4 = *(const float4*)(cr + k4);
            const float cs[4] = {c4.x, c4.y, c4.z, c4.w};
            #pragma unroll
            for (int kk = 0; kk < 4; kk++) {
                float4 w4 = *(const float4*)(WoT + (k4 + kk) * 68 + j0);
                float2 cd = dup(cs[kk]);
                fma2(olo, make_float2(w4.x, w4.y), cd);
                fma2(ohi, make_float2(w4.z, w4.w), cd);
            }
        }
        float4 o = make_float4(olo.x + __ldg(bo + j0),     olo.y + __ldg(bo + j0 + 1),
                               ohi.x + __ldg(bo + j0 + 2), ohi.y + __ldg(bo + j0 + 3));
        *(float4*)(out + (m0 + r) * H_ + j0) = o;
    }
}

// ------------------------------ launch -------------------------------------
extern "C" void kernel_launch(void* const* d_in, const int* in_sizes, int n_in,
                              void* d_out, int out_size)
{
    const float* fin  = (const float*)d_in[0];
    const int*   batch= (const int*)  d_in[1];
    const float* bpre = (const float*)d_in[2];
    const float* bvin = (const float*)d_in[3];
    const float* Wf   = (const float*)d_in[4];
    const float* bf   = (const float*)d_in[5];
    const float* Wb   = (const float*)d_in[6];
    const float* bb   = (const float*)d_in[7];
    const float* Wbv  = (const float*)d_in[8];
    const float* bbv  = (const float*)d_in[9];
    const float* Wo   = (const float*)d_in[10];
    const float* bo   = (const float*)d_in[11];
    float* out = (float*)d_out;

    const int msm = 46320 * sizeof(float);    // 185.3 KB
    cudaFuncSetAttribute(main_kernel, cudaFuncAttributeMaxDynamicSharedMemorySize, msm);

    main_kernel<<<M_ / TMR, NTHR, msm>>>(batch, bvin, Wbv, bbv, Wo, bo,
                                         fin, Wf, bf, bpre, Wb, bb, out);
}